// round 16
// baseline (speedup 1.0000x reference)
#include <cuda_runtime.h>
#include <cuda_bf16.h>
#include <mma.h>
#include <math.h>
#include <stdint.h>

// ---------------- model constants ----------------
#define D_MODEL 768
#define N_LAYER 4
#define D_STATE 16
#define D_CONV 4
#define DT_RANK 48
#define D_INNER 1536
#define B_SZ 2
#define L_SEQ 1024
#define N_MELS 80
#define M_ROWS (B_SZ * L_SEQ)              // 2048
#define XDBL_COLS (DT_RANK + 2 * D_STATE)  // 80

// weight split-buffer offsets (bf16 elements)
#define W_IN_OFF   0
#define W_XP_OFF   (N_LAYER * D_MODEL * 2 * D_INNER)
#define W_DT_OFF   (W_XP_OFF + N_LAYER * D_INNER * XDBL_COLS)
#define W_OUT_OFF  (W_DT_OFF + N_LAYER * DT_RANK * D_INNER)
#define W_HEAD_OFF (W_OUT_OFF + N_LAYER * D_INNER * D_MODEL)
#define W_TOTAL    (W_HEAD_OFF + D_MODEL * N_MELS)

#define XZP_STRIDE ((long)M_ROWS * 2 * D_INNER)   // stride between xz partials

// ---------------- scratch (device globals; no runtime alloc) ----------------
__device__ float g_x[M_ROWS * D_MODEL];
__device__ float g_xzp[3 * M_ROWS * 2 * D_INNER];  // in_proj split-K3 partials
__device__ float g_xi[M_ROWS * D_INNER];
__device__ float g_xdbl[M_ROWS * XDBL_COLS];
__device__ float g_delta[M_ROWS * D_INNER];
__device__ float g_part[16 * M_ROWS * XDBL_COLS > 3 * M_ROWS * D_MODEL
                        ? 16 * M_ROWS * XDBL_COLS : 3 * M_ROWS * D_MODEL];
__device__ __nv_bfloat16 g_Ah[M_ROWS * D_INNER];
__device__ __nv_bfloat16 g_Al[M_ROWS * D_INNER];
__device__ __nv_bfloat16 g_WBh[W_TOTAL];
__device__ __nv_bfloat16 g_WBl[W_TOTAL];

__device__ __forceinline__ void split_bf16(float v, __nv_bfloat16& hi, __nv_bfloat16& lo) {
    __nv_bfloat16 h = __float2bfloat16(v);
    float r = v - __bfloat162float(h);
    hi = h;
    lo = __float2bfloat16(r);
}

__device__ __forceinline__ void cpa16(uint32_t dst, const void* src, int valid) {
    asm volatile("cp.async.ca.shared.global [%0], [%1], 16, %2;"
                 :: "r"(dst), "l"(src), "r"(valid));
}

// ---------------- WMMA bf16 GEMM, 2-stage cp.async pipeline ----------------
__global__ __launch_bounds__(256, 2)
void wmma_gemm_bf16(int M, int N, int K, int kchunk,
                    const __nv_bfloat16* __restrict__ Ah,
                    const __nv_bfloat16* __restrict__ Al, int lda,
                    const __nv_bfloat16* __restrict__ Bh,
                    const __nv_bfloat16* __restrict__ Bl, int ldb,
                    float* __restrict__ C, int ldc)
{
    using namespace nvcuda;
    constexpr int SA = 40;
    constexpr int SB = 136;
    constexpr int OFF_AH = 0;
    constexpr int OFF_AL = 128 * SA * 2;
    constexpr int OFF_BH = 2 * 128 * SA * 2;
    constexpr int OFF_BL = OFF_BH + 32 * SB * 2;
    constexpr int STAGE  = OFF_BL + 32 * SB * 2;   // 37888

    extern __shared__ char sm[];
    const uint32_t smb = (uint32_t)__cvta_generic_to_shared(sm);

    const int t    = threadIdx.x;
    const int warp = t >> 5;
    const int wm   = warp >> 2;
    const int wn   = warp & 3;
    const int row0 = blockIdx.y * 128;
    const int col0 = blockIdx.x * 128;

    const int k_lo = blockIdx.z * kchunk;
    const int k_hi = min(K, k_lo + kchunk);
    const int KT   = (k_hi - k_lo + 31) / 32;
    C += (long)blockIdx.z * M * ldc;

    wmma::fragment<wmma::accumulator, 16, 16, 16, float> acc[4][2];
#pragma unroll
    for (int i = 0; i < 4; i++)
#pragma unroll
        for (int j = 0; j < 2; j++) wmma::fill_fragment(acc[i][j], 0.0f);

    const int arow = t >> 2,  ask = t & 3;
    const int brow = t >> 4,  bsk = t & 15;

    auto issue_stage = [&](int st, int k0) {
        uint32_t base = smb + st * STAGE;
#pragma unroll
        for (int ss = 0; ss < 2; ss++) {
            int row = arow + ss * 64;
            int kk = k0 + ask * 8;
            int valid = (k_hi - kk) * 2;
            valid = valid < 0 ? 0 : (valid > 16 ? 16 : valid);
            long srcoff = valid ? ((long)(row0 + row) * lda + kk) : 0;
            cpa16(base + OFF_AH + row * (SA * 2) + ask * 16, Ah + srcoff, valid);
            cpa16(base + OFF_AL + row * (SA * 2) + ask * 16, Al + srcoff, valid);
        }
#pragma unroll
        for (int ss = 0; ss < 2; ss++) {
            int row = brow + ss * 16;
            int nn = col0 + bsk * 8;
            int valid = (k0 + row < k_hi) ? (N - nn) * 2 : 0;
            valid = valid < 0 ? 0 : (valid > 16 ? 16 : valid);
            long srcoff = valid ? ((long)(k0 + row) * ldb + nn) : 0;
            cpa16(base + OFF_BH + row * (SB * 2) + bsk * 16, Bh + srcoff, valid);
            cpa16(base + OFF_BL + row * (SB * 2) + bsk * 16, Bl + srcoff, valid);
        }
        asm volatile("cp.async.commit_group;" ::: "memory");
    };

    issue_stage(0, k_lo);

    for (int kt = 0; kt < KT; kt++) {
        asm volatile("cp.async.wait_group 0;" ::: "memory");
        __syncthreads();
        if (kt + 1 < KT) issue_stage((kt + 1) & 1, k_lo + (kt + 1) * 32);

        const char* buf = sm + (kt & 1) * STAGE;
        const __nv_bfloat16* pAh = (const __nv_bfloat16*)(buf + OFF_AH);
        const __nv_bfloat16* pAl = (const __nv_bfloat16*)(buf + OFF_AL);
        const __nv_bfloat16* pBh = (const __nv_bfloat16*)(buf + OFF_BH);
        const __nv_bfloat16* pBl = (const __nv_bfloat16*)(buf + OFF_BL);

#pragma unroll
        for (int ks = 0; ks < 2; ks++) {
            wmma::fragment<wmma::matrix_b, 16, 16, 16, __nv_bfloat16, wmma::row_major> fbh[2], fbl[2];
#pragma unroll
            for (int j = 0; j < 2; j++) {
                wmma::load_matrix_sync(fbh[j], pBh + (ks * 16) * SB + wn * 32 + j * 16, SB);
                wmma::load_matrix_sync(fbl[j], pBl + (ks * 16) * SB + wn * 32 + j * 16, SB);
            }
#pragma unroll
            for (int i = 0; i < 4; i++) {
                wmma::fragment<wmma::matrix_a, 16, 16, 16, __nv_bfloat16, wmma::row_major> fah, fal;
                wmma::load_matrix_sync(fah, pAh + (wm * 64 + i * 16) * SA + ks * 16, SA);
                wmma::load_matrix_sync(fal, pAl + (wm * 64 + i * 16) * SA + ks * 16, SA);
#pragma unroll
                for (int j = 0; j < 2; j++) wmma::mma_sync(acc[i][j], fah, fbh[j], acc[i][j]);
#pragma unroll
                for (int j = 0; j < 2; j++) wmma::mma_sync(acc[i][j], fah, fbl[j], acc[i][j]);
#pragma unroll
                for (int j = 0; j < 2; j++) wmma::mma_sync(acc[i][j], fal, fbh[j], acc[i][j]);
            }
        }
    }

#pragma unroll
    for (int i = 0; i < 4; i++)
#pragma unroll
        for (int j = 0; j < 2; j++) {
            int gm = row0 + wm * 64 + i * 16;
            int gn = col0 + wn * 32 + j * 16;
            if (gn + 16 <= N)
                wmma::store_matrix_sync(C + (long)gm * ldc + gn, acc[i][j],
                                        ldc, wmma::mem_row_major);
        }
}

// ---------------- fused small kernels ----------------
// split ALL weight tensors in one launch
__global__ void split_weights_kernel(const float* __restrict__ w_in,
                                     const float* __restrict__ w_xp,
                                     const float* __restrict__ w_dt,
                                     const float* __restrict__ w_out,
                                     const float* __restrict__ w_head)
{
    long i = (long)blockIdx.x * blockDim.x + threadIdx.x;
    if (i >= W_TOTAL) return;
    float v;
    if (i < W_XP_OFF)        v = w_in[i - W_IN_OFF];
    else if (i < W_DT_OFF)   v = w_xp[i - W_XP_OFF];
    else if (i < W_OUT_OFF)  v = w_dt[i - W_DT_OFF];
    else if (i < W_HEAD_OFF) v = w_out[i - W_OUT_OFF];
    else                     v = w_head[i - W_HEAD_OFF];
    __nv_bfloat16 h, l;
    split_bf16(v, h, l);
    g_WBh[i] = h; g_WBl[i] = l;
}

// embed + rmsnorm + split (layer 0 input)
__global__ void embed_norm_kernel(const int* __restrict__ ids,
                                  const float* __restrict__ emb,
                                  const float* __restrict__ w)
{
    __shared__ float red[256];
    int row = blockIdx.x;
    int id = ids[row];
    const float* er = emb + (long)id * D_MODEL;
    float s = 0.0f;
    for (int c = threadIdx.x; c < D_MODEL; c += blockDim.x) {
        float v = er[c];
        g_x[row * D_MODEL + c] = v;
        s += v * v;
    }
    red[threadIdx.x] = s;
    __syncthreads();
    for (int off = 128; off > 0; off >>= 1) {
        if (threadIdx.x < off) red[threadIdx.x] += red[threadIdx.x + off];
        __syncthreads();
    }
    float scale = rsqrtf(red[0] / (float)D_MODEL + 1e-5f);
    for (int c = threadIdx.x; c < D_MODEL; c += blockDim.x) {
        __nv_bfloat16 h, l;
        split_bf16(er[c] * scale * w[c], h, l);
        g_Ah[row * D_MODEL + c] = h;
        g_Al[row * D_MODEL + c] = l;
    }
}

// reduce split-K(16) partials of x_proj -> g_xdbl, and split first 48 cols
__global__ void reduce_xdbl_kernel(void)
{
    const int cnt = M_ROWS * XDBL_COLS;
    int i = blockIdx.x * blockDim.x + threadIdx.x;
    if (i >= cnt) return;
    float s = 0.0f;
#pragma unroll
    for (int k = 0; k < 16; k++) s += g_part[(long)k * cnt + i];
    g_xdbl[i] = s;
    int row = i / XDBL_COLS, c = i % XDBL_COLS;
    if (c < DT_RANK) {
        __nv_bfloat16 h, l;
        split_bf16(s, h, l);
        g_Ah[row * DT_RANK + c] = h;
        g_Al[row * DT_RANK + c] = l;
    }
}

// reduce split-K(3) out_proj partials + residual + rmsnorm(w) + split
__global__ void reduce_res_norm_kernel(const float* __restrict__ w)
{
    __shared__ float red[256];
    const int cnt = M_ROWS * D_MODEL;
    int row = blockIdx.x;
    float s = 0.0f;
    for (int c = threadIdx.x; c < D_MODEL; c += blockDim.x) {
        int i = row * D_MODEL + c;
        float v = g_part[i] + g_part[cnt + i] + g_part[2 * (long)cnt + i] + g_x[i];
        g_x[i] = v;
        s += v * v;
    }
    red[threadIdx.x] = s;
    __syncthreads();
    for (int off = 128; off > 0; off >>= 1) {
        if (threadIdx.x < off) red[threadIdx.x] += red[threadIdx.x + off];
        __syncthreads();
    }
    float scale = rsqrtf(red[0] / (float)D_MODEL + 1e-5f);
    for (int c = threadIdx.x; c < D_MODEL; c += blockDim.x) {
        int i = row * D_MODEL + c;
        __nv_bfloat16 h, l;
        split_bf16(g_x[i] * scale * w[c], h, l);
        g_Ah[i] = h;
        g_Al[i] = l;
    }
}

// reduce split-K(8) head partials -> out
__global__ void reduce_head_kernel(float* __restrict__ outp)
{
    const int cnt = M_ROWS * N_MELS;
    int i = blockIdx.x * blockDim.x + threadIdx.x;
    if (i >= cnt) return;
    float s = 0.0f;
#pragma unroll
    for (int k = 0; k < 8; k++) s += g_part[(long)k * cnt + i];
    outp[i] = s;
}

// conv + silu; 4 consecutive l per thread (tap reuse); xz = sum of 3 partials
__global__ void conv_silu_kernel(const float* __restrict__ cw,
                                 const float* __restrict__ cb)
{
    const int total = (M_ROWS / 4) * D_INNER;
    int i = blockIdx.x * blockDim.x + threadIdx.x;
    if (i >= total) return;
    int d = i % D_INNER;
    int g = i / D_INNER;          // row-group index; rows g*4 .. g*4+3 (same b)
    int row0 = g * 4;
    int l0 = row0 % L_SEQ;

    // xz values for l = l0-3 .. l0+3 (7 taps window)
    float xv[7];
#pragma unroll
    for (int tsp = 0; tsp < 7; tsp++) {
        int ll = l0 - 3 + tsp;
        float v = 0.0f;
        if (ll >= 0) {
            long idx = (long)(row0 - 3 + tsp) * (2 * D_INNER) + d;
            v = g_xzp[idx] + g_xzp[XZP_STRIDE + idx] + g_xzp[2 * XZP_STRIDE + idx];
        }
        xv[tsp] = v;
    }

    float w0 = cw[d * D_CONV + 0];
    float w1 = cw[d * D_CONV + 1];
    float w2 = cw[d * D_CONV + 2];
    float w3 = cw[d * D_CONV + 3];
    float bias = cb[d];

#pragma unroll
    for (int j = 0; j < 4; j++) {
        float acc = bias;
        acc = fmaf(xv[j + 0], w0, acc);
        acc = fmaf(xv[j + 1], w1, acc);
        acc = fmaf(xv[j + 2], w2, acc);
        acc = fmaf(xv[j + 3], w3, acc);
        float sg = 1.0f / (1.0f + __expf(-acc));
        float v = acc * sg;
        long o = (long)(row0 + j) * D_INNER + d;
        g_xi[o] = v;
        __nv_bfloat16 h, lo;
        split_bf16(v, h, lo);
        g_Ah[o] = h; g_Al[o] = lo;
    }
}

// ---------------- selective scan ------------------------------------------
__device__ __forceinline__ float softplus_bias(float raw, float bias) {
    float v = raw + bias;
    return (v > 30.0f) ? v : log1pf(__expf(v));
}

__global__ __launch_bounds__(256)
void scan_kernel(const float* __restrict__ A_log,
                 const float* __restrict__ Dp,
                 const float* __restrict__ dtb)
{
    __shared__ float sTot[16][17];
    __shared__ float pTot[16][17];
    __shared__ float dt_s[L_SEQ];
    __shared__ float u_s[L_SEQ];

    const int tid = threadIdx.x;
    const int c = tid >> 4;
    const int n = tid & 15;
    const int bd = blockIdx.x;
    const int b = bd / D_INNER;
    const int d = bd % D_INNER;
    const float bias = dtb[d];
    const long base = (long)b * L_SEQ;

    for (int l = tid; l < L_SEQ; l += 256) {
        dt_s[l] = softplus_bias(g_delta[(base + l) * D_INNER + d], bias);
        u_s[l]  = g_xi[(base + l) * D_INNER + d];
    }
    __syncthreads();

    const float A_dn = -__expf(A_log[d * D_STATE + n]);
    const int CH = L_SEQ / 16;
    const int lg0 = c * CH;
    const long rowbase = base + lg0;

    float sloc = 0.0f;
    for (int i = 0; i < CH; i++) {
        float a = fmaxf(dt_s[lg0 + i] * A_dn, -20.0f);
        if (lg0 + i > 0) sloc += a;
    }
    sTot[n][c] = sloc;
    __syncthreads();
    float soff = 0.0f;
#pragma unroll
    for (int cc = 0; cc < 16; cc++)
        if (cc < c) soff += sTot[n][cc];

    sloc = 0.0f;
    float Ploc = 0.0f;
    for (int i = 0; i < CH; i++) {
        float dt = dt_s[lg0 + i];
        float u  = u_s[lg0 + i];
        float Bn = g_xdbl[(rowbase + i) * XDBL_COLS + DT_RANK + n];
        float a = fmaxf(dt * A_dn, -20.0f);
        if (lg0 + i > 0) sloc += a;
        float e = __expf(soff + sloc);
        Ploc += __fdividef(dt * u * Bn, e + 1e-12f);
    }
    pTot[n][c] = Ploc;
    __syncthreads();
    float Poff = 0.0f;
#pragma unroll
    for (int cc = 0; cc < 16; cc++)
        if (cc < c) Poff += pTot[n][cc];

    const float Dd = Dp[d];

    sloc = 0.0f;
    Ploc = 0.0f;
    for (int i = 0; i < CH; i++) {
        long row = rowbase + i;
        float dt = dt_s[lg0 + i];
        float u  = u_s[lg0 + i];
        float Bn = g_xdbl[row * XDBL_COLS + DT_RANK + n];
        float Cn = g_xdbl[row * XDBL_COLS + DT_RANK + D_STATE + n];
        float a = fmaxf(dt * A_dn, -20.0f);
        if (lg0 + i > 0) sloc += a;
        float e = __expf(soff + sloc);
        Ploc += __fdividef(dt * u * Bn, e + 1e-12f);
        float x = (Poff + Ploc) * e;
        float yp = x * Cn;
#pragma unroll
        for (int off = 8; off >= 1; off >>= 1)
            yp += __shfl_xor_sync(0xffffffffu, yp, off, 16);
        if (n == 0) {
            long ri = row * (2 * D_INNER) + D_INNER + d;
            float r = g_xzp[ri] + g_xzp[XZP_STRIDE + ri] + g_xzp[2 * XZP_STRIDE + ri];
            float sr = r / (1.0f + __expf(-r));
            float yv = (yp + u * Dd) * sr;
            __nv_bfloat16 h, l;
            split_bf16(yv, h, l);
            g_Ah[row * D_INNER + d] = h;
            g_Al[row * D_INNER + d] = l;
        }
    }
}

// ---------------- host side ----------------
static inline void* sym(const void* s)
{
    void* p = nullptr;
    cudaGetSymbolAddress(&p, s);
    return p;
}

#define GEMM_SMEM (2 * 37888)

static void launch_gemm(int M, int N, int K, int splits,
                        const __nv_bfloat16* Ah, const __nv_bfloat16* Al, int lda,
                        const __nv_bfloat16* Bh, const __nv_bfloat16* Bl, int ldb,
                        float* C, int ldc)
{
    int kchunk = (K + splits - 1) / splits;
    dim3 grid((N + 127) / 128, M / 128, splits);
    wmma_gemm_bf16<<<grid, 256, GEMM_SMEM>>>(M, N, K, kchunk,
                                             Ah, Al, lda, Bh, Bl, ldb, C, ldc);
}

extern "C" void kernel_launch(void* const* d_in, const int* in_sizes, int n_in,
                              void* d_out, int out_size)
{
    const int*   input_ids = (const int*)  d_in[0];
    const float* embedding = (const float*)d_in[1];
    const float* rms_w     = (const float*)d_in[2];
    const float* in_proj_w = (const float*)d_in[3];
    const float* conv_w    = (const float*)d_in[4];
    const float* conv_b    = (const float*)d_in[5];
    const float* x_proj_w  = (const float*)d_in[6];
    const float* dt_proj_w = (const float*)d_in[7];
    const float* dt_proj_b = (const float*)d_in[8];
    const float* A_log     = (const float*)d_in[9];
    const float* D_param   = (const float*)d_in[10];
    const float* out_proj_w= (const float*)d_in[11];
    const float* norm_f_w  = (const float*)d_in[12];
    const float* head_w    = (const float*)d_in[13];
    float* out = (float*)d_out;

    float* pxzp   = (float*)sym(g_xzp);
    float* pdelta = (float*)sym(g_delta);
    float* ppart  = (float*)sym(g_part);
    __nv_bfloat16* pAh  = (__nv_bfloat16*)sym(g_Ah);
    __nv_bfloat16* pAl  = (__nv_bfloat16*)sym(g_Al);
    __nv_bfloat16* pWBh = (__nv_bfloat16*)sym(g_WBh);
    __nv_bfloat16* pWBl = (__nv_bfloat16*)sym(g_WBl);

    cudaFuncSetAttribute(wmma_gemm_bf16,
                         cudaFuncAttributeMaxDynamicSharedMemorySize, GEMM_SMEM);

    // split all weights in one launch
    split_weights_kernel<<<(W_TOTAL + 255) / 256, 256>>>(
        in_proj_w, x_proj_w, dt_proj_w, out_proj_w, head_w);

    // embed + rmsnorm(layer0) + split
    embed_norm_kernel<<<M_ROWS, 256>>>(input_ids, embedding, rms_w);

    for (int i = 0; i < N_LAYER; i++) {
        const float* cw  = conv_w    + (long)i * D_INNER * D_CONV;
        const float* cb  = conv_b    + (long)i * D_INNER;
        const float* dtb = dt_proj_b + (long)i * D_INNER;
        const float* al  = A_log     + (long)i * D_INNER * D_STATE;
        const float* dp  = D_param   + (long)i * D_INNER;
        const __nv_bfloat16* iwh = pWBh + W_IN_OFF  + (long)i * D_MODEL * 2 * D_INNER;
        const __nv_bfloat16* iwl = pWBl + W_IN_OFF  + (long)i * D_MODEL * 2 * D_INNER;
        const __nv_bfloat16* xph = pWBh + W_XP_OFF  + (long)i * D_INNER * XDBL_COLS;
        const __nv_bfloat16* xpl = pWBl + W_XP_OFF  + (long)i * D_INNER * XDBL_COLS;
        const __nv_bfloat16* dth = pWBh + W_DT_OFF  + (long)i * DT_RANK * D_INNER;
        const __nv_bfloat16* dtl = pWBl + W_DT_OFF  + (long)i * DT_RANK * D_INNER;
        const __nv_bfloat16* owh = pWBh + W_OUT_OFF + (long)i * D_INNER * D_MODEL;
        const __nv_bfloat16* owl = pWBl + W_OUT_OFF + (long)i * D_INNER * D_MODEL;

        // in_proj split-K3 -> g_xzp partials (reduce fused into conv & scan)
        launch_gemm(M_ROWS, 2 * D_INNER, D_MODEL, 3, pAh, pAl, D_MODEL,
                    iwh, iwl, 2 * D_INNER, pxzp, 2 * D_INNER);

        // conv + silu (sums 3 xz partials, 4 l per thread) -> xi + split A
        {
            int total = (M_ROWS / 4) * D_INNER;
            conv_silu_kernel<<<(total + 255) / 256, 256>>>(cw, cb);
        }

        // x_proj split-K16 -> partials; reduce + split48
        launch_gemm(M_ROWS, XDBL_COLS, D_INNER, 16, pAh, pAl, D_INNER,
                    xph, xpl, XDBL_COLS, ppart, XDBL_COLS);
        {
            int rcount = M_ROWS * XDBL_COLS;
            reduce_xdbl_kernel<<<(rcount + 255) / 256, 256>>>();
        }

        // dt_proj: delta_raw = xdbl48 @ dt_w  (no split, K=48)
        launch_gemm(M_ROWS, D_INNER, DT_RANK, 1, pAh, pAl, DT_RANK,
                    dth, dtl, D_INNER, pdelta, D_INNER);

        // scan (softplus via smem pre-pass; gate r from 3 xz partials)
        scan_kernel<<<B_SZ * D_INNER, 256>>>(al, dp, dtb);

        // out_proj split-K3 -> partials
        launch_gemm(M_ROWS, D_MODEL, D_INNER, 3, pAh, pAl, D_INNER,
                    owh, owl, D_MODEL, ppart, D_MODEL);

        // reduce(3) + residual + next rmsnorm + split
        const float* nw = (i + 1 < N_LAYER) ? (rms_w + (long)(i + 1) * D_MODEL)
                                            : norm_f_w;
        reduce_res_norm_kernel<<<M_ROWS, 256>>>(nw);
    }

    // head split-K8 + reduce -> out
    launch_gemm(M_ROWS, N_MELS, D_MODEL, 8, pAh, pAl, D_MODEL,
                pWBh + W_HEAD_OFF, pWBl + W_HEAD_OFF, N_MELS, ppart, N_MELS);
    {
        int rcount = M_ROWS * N_MELS;
        reduce_head_kernel<<<(rcount + 255) / 256, 256>>>(out);
    }
}

// round 17
// speedup vs baseline: 1.0184x; 1.0184x over previous
#include <cuda_runtime.h>
#include <cuda_bf16.h>
#include <mma.h>
#include <math.h>
#include <stdint.h>

// ---------------- model constants ----------------
#define D_MODEL 768
#define N_LAYER 4
#define D_STATE 16
#define D_CONV 4
#define DT_RANK 48
#define D_INNER 1536
#define B_SZ 2
#define L_SEQ 1024
#define N_MELS 80
#define M_ROWS (B_SZ * L_SEQ)              // 2048
#define XDBL_COLS (DT_RANK + 2 * D_STATE)  // 80

// weight split-buffer offsets (bf16 elements)
#define W_IN_OFF   0
#define W_XP_OFF   (N_LAYER * D_MODEL * 2 * D_INNER)
#define W_DT_OFF   (W_XP_OFF + N_LAYER * D_INNER * XDBL_COLS)
#define W_OUT_OFF  (W_DT_OFF + N_LAYER * DT_RANK * D_INNER)
#define W_HEAD_OFF (W_OUT_OFF + N_LAYER * D_INNER * D_MODEL)
#define W_TOTAL    (W_HEAD_OFF + D_MODEL * N_MELS)

#define XZP_STRIDE ((long)M_ROWS * 2 * D_INNER)   // stride between xz partials

// ---------------- scratch (device globals; no runtime alloc) ----------------
__device__ float g_x[M_ROWS * D_MODEL];
__device__ float g_xzp[2 * M_ROWS * 2 * D_INNER];  // in_proj split-K2 partials
__device__ float g_xi[M_ROWS * D_INNER];
__device__ float g_xdbl[M_ROWS * XDBL_COLS];
__device__ float g_delta[M_ROWS * D_INNER];
__device__ float g_part[16 * M_ROWS * XDBL_COLS > 3 * M_ROWS * D_MODEL
                        ? 16 * M_ROWS * XDBL_COLS : 3 * M_ROWS * D_MODEL];
__device__ __nv_bfloat16 g_Ah[M_ROWS * D_INNER];
__device__ __nv_bfloat16 g_Al[M_ROWS * D_INNER];
__device__ __nv_bfloat16 g_WBh[W_TOTAL];
__device__ __nv_bfloat16 g_WBl[W_TOTAL];

__device__ __forceinline__ void split_bf16(float v, __nv_bfloat16& hi, __nv_bfloat16& lo) {
    __nv_bfloat16 h = __float2bfloat16(v);
    float r = v - __bfloat162float(h);
    hi = h;
    lo = __float2bfloat16(r);
}

__device__ __forceinline__ void cpa16(uint32_t dst, const void* src, int valid) {
    asm volatile("cp.async.ca.shared.global [%0], [%1], 16, %2;"
                 :: "r"(dst), "l"(src), "r"(valid));
}

// ---------------- WMMA bf16 GEMM, 2-stage cp.async pipeline ----------------
__global__ __launch_bounds__(256, 2)
void wmma_gemm_bf16(int M, int N, int K, int kchunk,
                    const __nv_bfloat16* __restrict__ Ah,
                    const __nv_bfloat16* __restrict__ Al, int lda,
                    const __nv_bfloat16* __restrict__ Bh,
                    const __nv_bfloat16* __restrict__ Bl, int ldb,
                    float* __restrict__ C, int ldc)
{
    using namespace nvcuda;
    constexpr int SA = 40;
    constexpr int SB = 136;
    constexpr int OFF_AH = 0;
    constexpr int OFF_AL = 128 * SA * 2;
    constexpr int OFF_BH = 2 * 128 * SA * 2;
    constexpr int OFF_BL = OFF_BH + 32 * SB * 2;
    constexpr int STAGE  = OFF_BL + 32 * SB * 2;   // 37888

    extern __shared__ char sm[];
    const uint32_t smb = (uint32_t)__cvta_generic_to_shared(sm);

    const int t    = threadIdx.x;
    const int warp = t >> 5;
    const int wm   = warp >> 2;
    const int wn   = warp & 3;
    const int row0 = blockIdx.y * 128;
    const int col0 = blockIdx.x * 128;

    const int k_lo = blockIdx.z * kchunk;
    const int k_hi = min(K, k_lo + kchunk);
    const int KT   = (k_hi - k_lo + 31) / 32;
    C += (long)blockIdx.z * M * ldc;

    wmma::fragment<wmma::accumulator, 16, 16, 16, float> acc[4][2];
#pragma unroll
    for (int i = 0; i < 4; i++)
#pragma unroll
        for (int j = 0; j < 2; j++) wmma::fill_fragment(acc[i][j], 0.0f);

    const int arow = t >> 2,  ask = t & 3;
    const int brow = t >> 4,  bsk = t & 15;

    auto issue_stage = [&](int st, int k0) {
        uint32_t base = smb + st * STAGE;
#pragma unroll
        for (int ss = 0; ss < 2; ss++) {
            int row = arow + ss * 64;
            int kk = k0 + ask * 8;
            int valid = (k_hi - kk) * 2;
            valid = valid < 0 ? 0 : (valid > 16 ? 16 : valid);
            long srcoff = valid ? ((long)(row0 + row) * lda + kk) : 0;
            cpa16(base + OFF_AH + row * (SA * 2) + ask * 16, Ah + srcoff, valid);
            cpa16(base + OFF_AL + row * (SA * 2) + ask * 16, Al + srcoff, valid);
        }
#pragma unroll
        for (int ss = 0; ss < 2; ss++) {
            int row = brow + ss * 16;
            int nn = col0 + bsk * 8;
            int valid = (k0 + row < k_hi) ? (N - nn) * 2 : 0;
            valid = valid < 0 ? 0 : (valid > 16 ? 16 : valid);
            long srcoff = valid ? ((long)(k0 + row) * ldb + nn) : 0;
            cpa16(base + OFF_BH + row * (SB * 2) + bsk * 16, Bh + srcoff, valid);
            cpa16(base + OFF_BL + row * (SB * 2) + bsk * 16, Bl + srcoff, valid);
        }
        asm volatile("cp.async.commit_group;" ::: "memory");
    };

    issue_stage(0, k_lo);

    for (int kt = 0; kt < KT; kt++) {
        asm volatile("cp.async.wait_group 0;" ::: "memory");
        __syncthreads();
        if (kt + 1 < KT) issue_stage((kt + 1) & 1, k_lo + (kt + 1) * 32);

        const char* buf = sm + (kt & 1) * STAGE;
        const __nv_bfloat16* pAh = (const __nv_bfloat16*)(buf + OFF_AH);
        const __nv_bfloat16* pAl = (const __nv_bfloat16*)(buf + OFF_AL);
        const __nv_bfloat16* pBh = (const __nv_bfloat16*)(buf + OFF_BH);
        const __nv_bfloat16* pBl = (const __nv_bfloat16*)(buf + OFF_BL);

#pragma unroll
        for (int ks = 0; ks < 2; ks++) {
            wmma::fragment<wmma::matrix_b, 16, 16, 16, __nv_bfloat16, wmma::row_major> fbh[2], fbl[2];
#pragma unroll
            for (int j = 0; j < 2; j++) {
                wmma::load_matrix_sync(fbh[j], pBh + (ks * 16) * SB + wn * 32 + j * 16, SB);
                wmma::load_matrix_sync(fbl[j], pBl + (ks * 16) * SB + wn * 32 + j * 16, SB);
            }
#pragma unroll
            for (int i = 0; i < 4; i++) {
                wmma::fragment<wmma::matrix_a, 16, 16, 16, __nv_bfloat16, wmma::row_major> fah, fal;
                wmma::load_matrix_sync(fah, pAh + (wm * 64 + i * 16) * SA + ks * 16, SA);
                wmma::load_matrix_sync(fal, pAl + (wm * 64 + i * 16) * SA + ks * 16, SA);
#pragma unroll
                for (int j = 0; j < 2; j++) wmma::mma_sync(acc[i][j], fah, fbh[j], acc[i][j]);
#pragma unroll
                for (int j = 0; j < 2; j++) wmma::mma_sync(acc[i][j], fah, fbl[j], acc[i][j]);
#pragma unroll
                for (int j = 0; j < 2; j++) wmma::mma_sync(acc[i][j], fal, fbh[j], acc[i][j]);
            }
        }
    }

#pragma unroll
    for (int i = 0; i < 4; i++)
#pragma unroll
        for (int j = 0; j < 2; j++) {
            int gm = row0 + wm * 64 + i * 16;
            int gn = col0 + wn * 32 + j * 16;
            if (gn + 16 <= N)
                wmma::store_matrix_sync(C + (long)gm * ldc + gn, acc[i][j],
                                        ldc, wmma::mem_row_major);
        }
}

// ---------------- fused small kernels ----------------
// split ALL weight tensors in one launch, 2 elements per thread
__global__ void split_weights_kernel(const float* __restrict__ w_in,
                                     const float* __restrict__ w_xp,
                                     const float* __restrict__ w_dt,
                                     const float* __restrict__ w_out,
                                     const float* __restrict__ w_head)
{
    long i0 = 2 * ((long)blockIdx.x * blockDim.x + threadIdx.x);
#pragma unroll
    for (int q = 0; q < 2; q++) {
        long i = i0 + q;
        if (i >= W_TOTAL) return;
        float v;
        if (i < W_XP_OFF)        v = w_in[i - W_IN_OFF];
        else if (i < W_DT_OFF)   v = w_xp[i - W_XP_OFF];
        else if (i < W_OUT_OFF)  v = w_dt[i - W_DT_OFF];
        else if (i < W_HEAD_OFF) v = w_out[i - W_OUT_OFF];
        else                     v = w_head[i - W_HEAD_OFF];
        __nv_bfloat16 h, l;
        split_bf16(v, h, l);
        g_WBh[i] = h; g_WBl[i] = l;
    }
}

// embed + rmsnorm + split (layer 0 input)
__global__ void embed_norm_kernel(const int* __restrict__ ids,
                                  const float* __restrict__ emb,
                                  const float* __restrict__ w)
{
    __shared__ float red[256];
    int row = blockIdx.x;
    int id = ids[row];
    const float* er = emb + (long)id * D_MODEL;
    float s = 0.0f;
    for (int c = threadIdx.x; c < D_MODEL; c += blockDim.x) {
        float v = er[c];
        g_x[row * D_MODEL + c] = v;
        s += v * v;
    }
    red[threadIdx.x] = s;
    __syncthreads();
    for (int off = 128; off > 0; off >>= 1) {
        if (threadIdx.x < off) red[threadIdx.x] += red[threadIdx.x + off];
        __syncthreads();
    }
    float scale = rsqrtf(red[0] / (float)D_MODEL + 1e-5f);
    for (int c = threadIdx.x; c < D_MODEL; c += blockDim.x) {
        __nv_bfloat16 h, l;
        split_bf16(er[c] * scale * w[c], h, l);
        g_Ah[row * D_MODEL + c] = h;
        g_Al[row * D_MODEL + c] = l;
    }
}

// reduce split-K(16) partials of x_proj -> g_xdbl, and split first 48 cols
__global__ void reduce_xdbl_kernel(void)
{
    const int cnt = M_ROWS * XDBL_COLS;
    int i = blockIdx.x * blockDim.x + threadIdx.x;
    if (i >= cnt) return;
    float s = 0.0f;
#pragma unroll
    for (int k = 0; k < 16; k++) s += g_part[(long)k * cnt + i];
    g_xdbl[i] = s;
    int row = i / XDBL_COLS, c = i % XDBL_COLS;
    if (c < DT_RANK) {
        __nv_bfloat16 h, l;
        split_bf16(s, h, l);
        g_Ah[row * DT_RANK + c] = h;
        g_Al[row * DT_RANK + c] = l;
    }
}

// reduce split-K(3) out_proj partials + residual + rmsnorm(w) + split
__global__ void reduce_res_norm_kernel(const float* __restrict__ w)
{
    __shared__ float red[256];
    const int cnt = M_ROWS * D_MODEL;
    int row = blockIdx.x;
    float s = 0.0f;
    for (int c = threadIdx.x; c < D_MODEL; c += blockDim.x) {
        int i = row * D_MODEL + c;
        float v = g_part[i] + g_part[cnt + i] + g_part[2 * (long)cnt + i] + g_x[i];
        g_x[i] = v;
        s += v * v;
    }
    red[threadIdx.x] = s;
    __syncthreads();
    for (int off = 128; off > 0; off >>= 1) {
        if (threadIdx.x < off) red[threadIdx.x] += red[threadIdx.x + off];
        __syncthreads();
    }
    float scale = rsqrtf(red[0] / (float)D_MODEL + 1e-5f);
    for (int c = threadIdx.x; c < D_MODEL; c += blockDim.x) {
        int i = row * D_MODEL + c;
        __nv_bfloat16 h, l;
        split_bf16(g_x[i] * scale * w[c], h, l);
        g_Ah[i] = h;
        g_Al[i] = l;
    }
}

// reduce split-K(8) head partials -> out
__global__ void reduce_head_kernel(float* __restrict__ outp)
{
    const int cnt = M_ROWS * N_MELS;
    int i = blockIdx.x * blockDim.x + threadIdx.x;
    if (i >= cnt) return;
    float s = 0.0f;
#pragma unroll
    for (int k = 0; k < 8; k++) s += g_part[(long)k * cnt + i];
    outp[i] = s;
}

// conv + silu; 4 consecutive l per thread (tap reuse); xz = sum of 2 partials
__global__ void conv_silu_kernel(const float* __restrict__ cw,
                                 const float* __restrict__ cb)
{
    const int total = (M_ROWS / 4) * D_INNER;
    int i = blockIdx.x * blockDim.x + threadIdx.x;
    if (i >= total) return;
    int d = i % D_INNER;
    int g = i / D_INNER;          // rows g*4 .. g*4+3 (same batch element)
    int row0 = g * 4;
    int l0 = row0 % L_SEQ;

    float xv[7];
#pragma unroll
    for (int tsp = 0; tsp < 7; tsp++) {
        int ll = l0 - 3 + tsp;
        float v = 0.0f;
        if (ll >= 0) {
            long idx = (long)(row0 - 3 + tsp) * (2 * D_INNER) + d;
            v = g_xzp[idx] + g_xzp[XZP_STRIDE + idx];
        }
        xv[tsp] = v;
    }

    float w0 = cw[d * D_CONV + 0];
    float w1 = cw[d * D_CONV + 1];
    float w2 = cw[d * D_CONV + 2];
    float w3 = cw[d * D_CONV + 3];
    float bias = cb[d];

#pragma unroll
    for (int j = 0; j < 4; j++) {
        float acc = bias;
        acc = fmaf(xv[j + 0], w0, acc);
        acc = fmaf(xv[j + 1], w1, acc);
        acc = fmaf(xv[j + 2], w2, acc);
        acc = fmaf(xv[j + 3], w3, acc);
        float sg = 1.0f / (1.0f + __expf(-acc));
        float v = acc * sg;
        long o = (long)(row0 + j) * D_INNER + d;
        g_xi[o] = v;
        __nv_bfloat16 h, lo;
        split_bf16(v, h, lo);
        g_Ah[o] = h; g_Al[o] = lo;
    }
}

// ---------------- selective scan ------------------------------------------
__device__ __forceinline__ float softplus_bias(float raw, float bias) {
    float v = raw + bias;
    return (v > 30.0f) ? v : log1pf(__expf(v));
}

__global__ __launch_bounds__(256)
void scan_kernel(const float* __restrict__ A_log,
                 const float* __restrict__ Dp,
                 const float* __restrict__ dtb)
{
    __shared__ float sTot[16][17];
    __shared__ float pTot[16][17];
    __shared__ float dt_s[L_SEQ];
    __shared__ float du_s[L_SEQ];   // dt * u, precomputed once
    __shared__ float u_s[L_SEQ];

    const int tid = threadIdx.x;
    const int c = tid >> 4;
    const int n = tid & 15;
    const int bd = blockIdx.x;
    const int b = bd / D_INNER;
    const int d = bd % D_INNER;
    const float bias = dtb[d];
    const long base = (long)b * L_SEQ;

    for (int l = tid; l < L_SEQ; l += 256) {
        float dt = softplus_bias(g_delta[(base + l) * D_INNER + d], bias);
        float u  = g_xi[(base + l) * D_INNER + d];
        dt_s[l] = dt;
        du_s[l] = dt * u;
        u_s[l]  = u;
    }
    __syncthreads();

    const float A_dn = -__expf(A_log[d * D_STATE + n]);
    const int CH = L_SEQ / 16;
    const int lg0 = c * CH;
    const long rowbase = base + lg0;

    float sloc = 0.0f;
    for (int i = 0; i < CH; i++) {
        float a = fmaxf(dt_s[lg0 + i] * A_dn, -20.0f);
        if (lg0 + i > 0) sloc += a;
    }
    sTot[n][c] = sloc;
    __syncthreads();
    float soff = 0.0f;
#pragma unroll
    for (int cc = 0; cc < 16; cc++)
        if (cc < c) soff += sTot[n][cc];

    sloc = 0.0f;
    float Ploc = 0.0f;
    for (int i = 0; i < CH; i++) {
        float du = du_s[lg0 + i];
        float Bn = g_xdbl[(rowbase + i) * XDBL_COLS + DT_RANK + n];
        float a = fmaxf(dt_s[lg0 + i] * A_dn, -20.0f);
        if (lg0 + i > 0) sloc += a;
        float e = __expf(soff + sloc);
        Ploc += __fdividef(du * Bn, e + 1e-12f);
    }
    pTot[n][c] = Ploc;
    __syncthreads();
    float Poff = 0.0f;
#pragma unroll
    for (int cc = 0; cc < 16; cc++)
        if (cc < c) Poff += pTot[n][cc];

    const float Dd = Dp[d];

    sloc = 0.0f;
    Ploc = 0.0f;
    for (int i = 0; i < CH; i++) {
        long row = rowbase + i;
        float du = du_s[lg0 + i];
        float Bn = g_xdbl[row * XDBL_COLS + DT_RANK + n];
        float Cn = g_xdbl[row * XDBL_COLS + DT_RANK + D_STATE + n];
        float a = fmaxf(dt_s[lg0 + i] * A_dn, -20.0f);
        if (lg0 + i > 0) sloc += a;
        float e = __expf(soff + sloc);
        Ploc += __fdividef(du * Bn, e + 1e-12f);
        float x = (Poff + Ploc) * e;
        float yp = x * Cn;
#pragma unroll
        for (int off = 8; off >= 1; off >>= 1)
            yp += __shfl_xor_sync(0xffffffffu, yp, off, 16);
        if (n == 0) {
            long ri = row * (2 * D_INNER) + D_INNER + d;
            float r = g_xzp[ri] + g_xzp[XZP_STRIDE + ri];
            float sr = r / (1.0f + __expf(-r));
            float yv = (yp + u_s[lg0 + i] * Dd) * sr;
            __nv_bfloat16 h, l;
            split_bf16(yv, h, l);
            g_Ah[row * D_INNER + d] = h;
            g_Al[row * D_INNER + d] = l;
        }
    }
}

// ---------------- host side ----------------
static inline void* sym(const void* s)
{
    void* p = nullptr;
    cudaGetSymbolAddress(&p, s);
    return p;
}

#define GEMM_SMEM (2 * 37888)

static void launch_gemm(int M, int N, int K, int splits,
                        const __nv_bfloat16* Ah, const __nv_bfloat16* Al, int lda,
                        const __nv_bfloat16* Bh, const __nv_bfloat16* Bl, int ldb,
                        float* C, int ldc)
{
    int kchunk = (K + splits - 1) / splits;
    dim3 grid((N + 127) / 128, M / 128, splits);
    wmma_gemm_bf16<<<grid, 256, GEMM_SMEM>>>(M, N, K, kchunk,
                                             Ah, Al, lda, Bh, Bl, ldb, C, ldc);
}

extern "C" void kernel_launch(void* const* d_in, const int* in_sizes, int n_in,
                              void* d_out, int out_size)
{
    const int*   input_ids = (const int*)  d_in[0];
    const float* embedding = (const float*)d_in[1];
    const float* rms_w     = (const float*)d_in[2];
    const float* in_proj_w = (const float*)d_in[3];
    const float* conv_w    = (const float*)d_in[4];
    const float* conv_b    = (const float*)d_in[5];
    const float* x_proj_w  = (const float*)d_in[6];
    const float* dt_proj_w = (const float*)d_in[7];
    const float* dt_proj_b = (const float*)d_in[8];
    const float* A_log     = (const float*)d_in[9];
    const float* D_param   = (const float*)d_in[10];
    const float* out_proj_w= (const float*)d_in[11];
    const float* norm_f_w  = (const float*)d_in[12];
    const float* head_w    = (const float*)d_in[13];
    float* out = (float*)d_out;

    float* pxzp   = (float*)sym(g_xzp);
    float* pdelta = (float*)sym(g_delta);
    float* ppart  = (float*)sym(g_part);
    __nv_bfloat16* pAh  = (__nv_bfloat16*)sym(g_Ah);
    __nv_bfloat16* pAl  = (__nv_bfloat16*)sym(g_Al);
    __nv_bfloat16* pWBh = (__nv_bfloat16*)sym(g_WBh);
    __nv_bfloat16* pWBl = (__nv_bfloat16*)sym(g_WBl);

    cudaFuncSetAttribute(wmma_gemm_bf16,
                         cudaFuncAttributeMaxDynamicSharedMemorySize, GEMM_SMEM);

    // split all weights in one launch (2 elems/thread)
    split_weights_kernel<<<(W_TOTAL / 2 + 255) / 256, 256>>>(
        in_proj_w, x_proj_w, dt_proj_w, out_proj_w, head_w);

    // embed + rmsnorm(layer0) + split
    embed_norm_kernel<<<M_ROWS, 256>>>(input_ids, embedding, rms_w);

    for (int i = 0; i < N_LAYER; i++) {
        const float* cw  = conv_w    + (long)i * D_INNER * D_CONV;
        const float* cb  = conv_b    + (long)i * D_INNER;
        const float* dtb = dt_proj_b + (long)i * D_INNER;
        const float* al  = A_log     + (long)i * D_INNER * D_STATE;
        const float* dp  = D_param   + (long)i * D_INNER;
        const __nv_bfloat16* iwh = pWBh + W_IN_OFF  + (long)i * D_MODEL * 2 * D_INNER;
        const __nv_bfloat16* iwl = pWBl + W_IN_OFF  + (long)i * D_MODEL * 2 * D_INNER;
        const __nv_bfloat16* xph = pWBh + W_XP_OFF  + (long)i * D_INNER * XDBL_COLS;
        const __nv_bfloat16* xpl = pWBl + W_XP_OFF  + (long)i * D_INNER * XDBL_COLS;
        const __nv_bfloat16* dth = pWBh + W_DT_OFF  + (long)i * DT_RANK * D_INNER;
        const __nv_bfloat16* dtl = pWBl + W_DT_OFF  + (long)i * DT_RANK * D_INNER;
        const __nv_bfloat16* owh = pWBh + W_OUT_OFF + (long)i * D_INNER * D_MODEL;
        const __nv_bfloat16* owl = pWBl + W_OUT_OFF + (long)i * D_INNER * D_MODEL;

        // in_proj split-K2 -> g_xzp partials (reduce fused into conv & scan)
        launch_gemm(M_ROWS, 2 * D_INNER, D_MODEL, 2, pAh, pAl, D_MODEL,
                    iwh, iwl, 2 * D_INNER, pxzp, 2 * D_INNER);

        // conv + silu (sums 2 xz partials, 4 l per thread) -> xi + split A
        {
            int total = (M_ROWS / 4) * D_INNER;
            conv_silu_kernel<<<(total + 255) / 256, 256>>>(cw, cb);
        }

        // x_proj split-K16 -> partials; reduce + split48
        launch_gemm(M_ROWS, XDBL_COLS, D_INNER, 16, pAh, pAl, D_INNER,
                    xph, xpl, XDBL_COLS, ppart, XDBL_COLS);
        {
            int rcount = M_ROWS * XDBL_COLS;
            reduce_xdbl_kernel<<<(rcount + 255) / 256, 256>>>();
        }

        // dt_proj: delta_raw = xdbl48 @ dt_w  (no split, K=48)
        launch_gemm(M_ROWS, D_INNER, DT_RANK, 1, pAh, pAl, DT_RANK,
                    dth, dtl, D_INNER, pdelta, D_INNER);

        // scan (softplus + du precomputed in smem; gate from 2 xz partials)
        scan_kernel<<<B_SZ * D_INNER, 256>>>(al, dp, dtb);

        // out_proj split-K3 -> partials
        launch_gemm(M_ROWS, D_MODEL, D_INNER, 3, pAh, pAl, D_INNER,
                    owh, owl, D_MODEL, ppart, D_MODEL);

        // reduce(3) + residual + next rmsnorm + split
        const float* nw = (i + 1 < N_LAYER) ? (rms_w + (long)(i + 1) * D_MODEL)
                                            : norm_f_w;
        reduce_res_norm_kernel<<<M_ROWS, 256>>>(nw);
    }

    // head split-K8 + reduce -> out
    launch_gemm(M_ROWS, N_MELS, D_MODEL, 8, pAh, pAl, D_MODEL,
                pWBh + W_HEAD_OFF, pWBl + W_HEAD_OFF, N_MELS, ppart, N_MELS);
    {
        int rcount = M_ROWS * N_MELS;
        reduce_head_kernel<<<(rcount + 255) / 256, 256>>>(out);
    }
}